// round 9
// baseline (speedup 1.0000x reference)
#include <cuda_runtime.h>
#include <math.h>

#define D_INNER 8192
#define D_MODEL 4096
#define DT_RANK 8
#define D_STATE 16
#define XP_DIM  (DT_RANK + 2 * D_STATE)   // 40

#define NB_WIN   4096
#define NB_WINX  2048
#define NB_XP    320
#define NB_SSM   64
#define NB_WOUT  4096
#define B_XP0    NB_WIN
#define B_SSM0   (B_XP0 + NB_XP)
#define B_WOUT0  (B_SSM0 + NB_SSM)
#define NB_TOT   (B_WOUT0 + NB_WOUT)      // 8576

// Scratch + flags
__device__ float g_x_conv[D_INNER];
__device__ float g_z_silu[D_INNER];
__device__ float g_xp[XP_DIM];
__device__ float g_y[D_INNER];
__device__ unsigned int c_winx, c_winz, c_xp, c_ssm, c_done;

__device__ __forceinline__ void spin_until(volatile unsigned int* p, unsigned int v) {
    while (*p < v) __nanosleep(64);
}

// ---------------------------------------------------------------------------
// ONE kernel, 4 phases by blockIdx, dependencies via counters.
// 128 threads, 32-reg budget, 8KB dynamic smem (used by ssm/wout phases).
// ---------------------------------------------------------------------------
__global__ __launch_bounds__(128, 16) void k_fused(
    const float* __restrict__ W_in,
    const float* __restrict__ x,
    const float* __restrict__ conv_buffer,
    const float* __restrict__ conv_w,
    const float* __restrict__ conv_b,
    const float* __restrict__ W_xp,
    const float* __restrict__ W_dt,
    const float* __restrict__ b_dt,
    const float* __restrict__ ssm_state,
    const float* __restrict__ A_log,
    const float* __restrict__ D_param,
    const float* __restrict__ W_out,
    float* __restrict__ out)
{
    extern __shared__ float sh[];
    const int b    = blockIdx.x;
    const int tid  = threadIdx.x;
    const int lane = tid & 31;
    const int warp = tid >> 5;

    if (b < NB_WIN) {
        // ---------------- Phase 1: xz = W_in @ x + conv/silu ----------------
        if (b < 32) out[b * 128 + tid] = 0.0f;            // zero out[0:4096]
        if (b == 0 && tid < XP_DIM) g_xp[tid] = 0.0f;

        const int row = b * 4 + warp;
        const float4* w4 = (const float4*)(W_in + (size_t)row * D_MODEL);
        const float4* x4 = (const float4*)x;

        float acc0 = 0.0f, acc1 = 0.0f;
        #pragma unroll
        for (int i = lane; i < D_MODEL / 4; i += 64) {
            float4 wa = __ldcs(&w4[i]);
            float4 wb = __ldcs(&w4[i + 32]);
            float4 va = x4[i];
            float4 vb = x4[i + 32];
            acc0 = fmaf(wa.x, va.x, acc0); acc0 = fmaf(wa.y, va.y, acc0);
            acc0 = fmaf(wa.z, va.z, acc0); acc0 = fmaf(wa.w, va.w, acc0);
            acc1 = fmaf(wb.x, vb.x, acc1); acc1 = fmaf(wb.y, vb.y, acc1);
            acc1 = fmaf(wb.z, vb.z, acc1); acc1 = fmaf(wb.w, vb.w, acc1);
        }
        float acc = acc0 + acc1;
        #pragma unroll
        for (int o = 16; o; o >>= 1) acc += __shfl_xor_sync(0xffffffffu, acc, o);

        if (lane == 0) {
            if (row < D_INNER) {
                float b1 = conv_buffer[row * 3 + 1];
                float b2 = conv_buffer[row * 3 + 2];
                float4 cw = ((const float4*)conv_w)[row];
                float s = fmaf(b1, cw.x, fmaf(b2, cw.y,
                           fmaf(acc, cw.z, fmaf(acc, cw.w, conv_b[row]))));
                g_x_conv[row] = s / (1.0f + expf(-s));
            } else {
                g_z_silu[row - D_INNER] = acc / (1.0f + expf(-acc));
            }
        }
        __syncthreads();
        if (tid == 0) {
            __threadfence();
            atomicAdd(b < NB_WINX ? &c_winx : &c_winz, 1u);
        }

    } else if (b < B_SSM0) {
        // ---------------- Phase 2: xp = W_xp @ x_conv (split-K) -------------
        const int idx = b - B_XP0;            // 0..319
        const int row = idx % XP_DIM;
        const int kb  = (idx / XP_DIM) * 1024;

        if (tid == 0) spin_until(&c_winx, NB_WINX);
        __syncthreads();
        __threadfence();

        const float4* w4 = (const float4*)(W_xp + (size_t)row * D_INNER + kb);
        const float4* v4 = (const float4*)(g_x_conv + kb);
        float acc = 0.0f;
        #pragma unroll
        for (int i = tid; i < 256; i += 128) {
            float4 w = __ldcs(&w4[i]);
            float4 v = __ldcg(&v4[i]);
            acc = fmaf(w.x, v.x, acc); acc = fmaf(w.y, v.y, acc);
            acc = fmaf(w.z, v.z, acc); acc = fmaf(w.w, v.w, acc);
        }
        #pragma unroll
        for (int o = 16; o; o >>= 1) acc += __shfl_xor_sync(0xffffffffu, acc, o);
        if (lane == 0) sh[warp] = acc;
        __syncthreads();
        if (tid == 0) {
            atomicAdd(&g_xp[row], sh[0] + sh[1] + sh[2] + sh[3]);
            __threadfence();
            atomicAdd(&c_xp, 1u);
        }

    } else if (b < B_WOUT0) {
        // ---------------- Phase 3: SSM update ------------------------------
        if (tid == 0) { spin_until(&c_xp, NB_XP); spin_until(&c_winz, NB_WIN - NB_WINX); }
        __syncthreads();
        __threadfence();
        if (tid < XP_DIM) sh[tid] = __ldcg(&g_xp[tid]);
        __syncthreads();

        const int ch = (b - B_SSM0) * 128 + tid;

        float dtr = b_dt[ch];
        const float4* wd4 = (const float4*)(W_dt + (size_t)ch * DT_RANK);
        float4 w0 = wd4[0], w1 = wd4[1];
        dtr = fmaf(w0.x, sh[0], dtr); dtr = fmaf(w0.y, sh[1], dtr);
        dtr = fmaf(w0.z, sh[2], dtr); dtr = fmaf(w0.w, sh[3], dtr);
        dtr = fmaf(w1.x, sh[4], dtr); dtr = fmaf(w1.y, sh[5], dtr);
        dtr = fmaf(w1.z, sh[6], dtr); dtr = fmaf(w1.w, sh[7], dtr);
        float dt = (dtr > 20.0f) ? dtr : log1pf(expf(dtr));

        const float xc = __ldcg(&g_x_conv[ch]);
        const float* al = A_log + (size_t)ch * D_STATE;
        const float* st = ssm_state + (size_t)ch * D_STATE;
        float* hout = out + D_MODEL + (size_t)ch * D_STATE;

        float acc = 0.0f;
        #pragma unroll
        for (int s = 0; s < D_STATE; s++) {
            float A    = -expf(al[s]);
            float abar = expf(dt * A);
            float h    = fmaf(abar, st[s], dt * sh[DT_RANK + s] * xc);
            hout[s] = h;
            acc = fmaf(h, sh[DT_RANK + D_STATE + s], acc);
        }
        g_y[ch] = fmaf(D_param[ch], xc, acc) * __ldcg(&g_z_silu[ch]);
        __syncthreads();
        if (tid == 0) { __threadfence(); atomicAdd(&c_ssm, 1u); }

    } else {
        // ---------------- Phase 4: out += W_out @ y ------------------------
        const int idx = b - B_WOUT0;          // 0..4095
        const int q   = idx >> 10;            // K-quarter 0..3
        const int row = (idx & 1023) * 4 + warp;
        const int kb4 = q * 512;              // quarter offset in float4s

        if (tid == 0) spin_until(&c_ssm, NB_SSM);
        __syncthreads();
        __threadfence();

        float4* sy = (float4*)sh;             // 512 float4 = 8KB
        const float4* y4 = (const float4*)g_y + kb4;
        #pragma unroll
        for (int i = tid; i < 512; i += 128) sy[i] = __ldcg(&y4[i]);
        __syncthreads();

        const float4* w4 = (const float4*)(W_out + (size_t)row * D_INNER) + kb4;
        float acc0 = 0.0f, acc1 = 0.0f;
        #pragma unroll
        for (int i = lane; i < 512; i += 64) {
            float4 wa = __ldcs(&w4[i]);
            float4 wb = __ldcs(&w4[i + 32]);
            float4 va = sy[i];
            float4 vb = sy[i + 32];
            acc0 = fmaf(wa.x, va.x, acc0); acc0 = fmaf(wa.y, va.y, acc0);
            acc0 = fmaf(wa.z, va.z, acc0); acc0 = fmaf(wa.w, va.w, acc0);
            acc1 = fmaf(wb.x, vb.x, acc1); acc1 = fmaf(wb.y, vb.y, acc1);
            acc1 = fmaf(wb.z, vb.z, acc1); acc1 = fmaf(wb.w, vb.w, acc1);
        }
        float acc = acc0 + acc1;
        #pragma unroll
        for (int o = 16; o; o >>= 1) acc += __shfl_xor_sync(0xffffffffu, acc, o);
        if (lane == 0) atomicAdd(&out[row], acc);

        __syncthreads();
        if (tid == 0) {
            unsigned int t = atomicAdd(&c_done, 1u);
            if (t == NB_WOUT - 1) {           // last block: reset for replay
                c_winx = 0; c_winz = 0; c_xp = 0; c_ssm = 0; c_done = 0;
                __threadfence();
            }
        }
    }
}

// ---------------------------------------------------------------------------
extern "C" void kernel_launch(void* const* d_in, const int* in_sizes, int n_in,
                              void* d_out, int out_size)
{
    const float* x           = (const float*)d_in[0];
    const float* ssm_state   = (const float*)d_in[1];
    const float* conv_buffer = (const float*)d_in[2];
    const float* W_in        = (const float*)d_in[3];
    const float* conv_w      = (const float*)d_in[4];
    const float* conv_b      = (const float*)d_in[5];
    const float* W_xp        = (const float*)d_in[6];
    const float* W_dt        = (const float*)d_in[7];
    const float* b_dt        = (const float*)d_in[8];
    const float* A_log       = (const float*)d_in[9];
    const float* D_param     = (const float*)d_in[10];
    const float* W_out       = (const float*)d_in[11];
    float* out = (float*)d_out;

    k_fused<<<NB_TOT, 128, 8192>>>(W_in, x, conv_buffer, conv_w, conv_b,
                                   W_xp, W_dt, b_dt, ssm_state, A_log,
                                   D_param, W_out, out);
}

// round 10
// speedup vs baseline: 1.1247x; 1.1247x over previous
#include <cuda_runtime.h>
#include <math.h>

#define D_INNER 8192
#define D_MODEL 4096
#define DT_RANK 8
#define D_STATE 16
#define XP_DIM  (DT_RANK + 2 * D_STATE)   // 40

#define NB_XP   320     // 40 rows x 8 K-chunks of 1024
#define NB_MID  384     // 320 xp + 64 ssm blocks (single wave)

// Scratch
__device__ float g_x_conv[D_INNER];
__device__ float g_z_silu[D_INNER];
__device__ float g_xp[XP_DIM];
__device__ float g_y[D_INNER];
__device__ unsigned int c_xp;

// ---------------------------------------------------------------------------
// Kernel 1: xz = W_in @ x (16384 x 4096) + fused conv/silu epilogue.
// Warp-per-row, 128thr, 16 blocks/SM. Blocks 0-31 zero out[0:4096];
// block 0 zeroes g_xp. grid = 4096.
// ---------------------------------------------------------------------------
__global__ __launch_bounds__(128, 16) void k_win(
    const float* __restrict__ W_in,
    const float* __restrict__ x,
    const float* __restrict__ conv_buffer,
    const float* __restrict__ conv_w,
    const float* __restrict__ conv_b,
    float* __restrict__ out)
{
    const int tid  = threadIdx.x;
    const int lane = tid & 31;
    const int warp = tid >> 5;
    if (blockIdx.x < 32) out[blockIdx.x * 128 + tid] = 0.0f;
    if (blockIdx.x == 0 && tid < XP_DIM) g_xp[tid] = 0.0f;

    const int row = blockIdx.x * 4 + warp;
    const float4* w4 = (const float4*)(W_in + (size_t)row * D_MODEL);
    const float4* x4 = (const float4*)x;

    float acc0 = 0.0f, acc1 = 0.0f;
    #pragma unroll
    for (int i = lane; i < D_MODEL / 4; i += 64) {
        float4 wa = __ldcs(&w4[i]);
        float4 wb = __ldcs(&w4[i + 32]);
        float4 va = x4[i];
        float4 vb = x4[i + 32];
        acc0 = fmaf(wa.x, va.x, acc0); acc0 = fmaf(wa.y, va.y, acc0);
        acc0 = fmaf(wa.z, va.z, acc0); acc0 = fmaf(wa.w, va.w, acc0);
        acc1 = fmaf(wb.x, vb.x, acc1); acc1 = fmaf(wb.y, vb.y, acc1);
        acc1 = fmaf(wb.z, vb.z, acc1); acc1 = fmaf(wb.w, vb.w, acc1);
    }
    float acc = acc0 + acc1;
    #pragma unroll
    for (int o = 16; o; o >>= 1) acc += __shfl_xor_sync(0xffffffffu, acc, o);

    if (lane == 0) {
        if (row < D_INNER) {
            float b1 = conv_buffer[row * 3 + 1];
            float b2 = conv_buffer[row * 3 + 2];
            float4 cw = ((const float4*)conv_w)[row];
            float s = fmaf(b1, cw.x, fmaf(b2, cw.y,
                       fmaf(acc, cw.z, fmaf(acc, cw.w, conv_b[row]))));
            g_x_conv[row] = s / (1.0f + expf(-s));
        } else {
            g_z_silu[row - D_INNER] = acc / (1.0f + expf(-acc));
        }
    }
}

// ---------------------------------------------------------------------------
// Kernel 2 (PDL secondary): xp GEMV (blocks 0-319) + SSM update (320-383).
// Single wave (384 blocks) so intra-kernel spin is safe. gridsync waits on
// k_win completion; ssm blocks additionally spin on c_xp (reset by k_wout).
// ---------------------------------------------------------------------------
__global__ __launch_bounds__(128, 16) void k_mid(
    const float* __restrict__ W_xp,
    const float* __restrict__ W_dt,
    const float* __restrict__ b_dt,
    const float* __restrict__ ssm_state,
    const float* __restrict__ A_log,
    const float* __restrict__ D_param,
    float* __restrict__ out)
{
    __shared__ float sh[XP_DIM];
    const int b    = blockIdx.x;
    const int tid  = threadIdx.x;
    const int lane = tid & 31;
    const int warp = tid >> 5;

    cudaGridDependencySynchronize();    // k_win outputs visible after this

    if (b < NB_XP) {
        // xp = W_xp @ x_conv, split-K chunk
        const int row = b % XP_DIM;
        const int kb  = (b / XP_DIM) * 1024;
        const float4* w4 = (const float4*)(W_xp + (size_t)row * D_INNER + kb);
        const float4* v4 = (const float4*)(g_x_conv + kb);
        float acc = 0.0f;
        #pragma unroll
        for (int i = tid; i < 256; i += 128) {
            float4 w = __ldcs(&w4[i]);
            float4 v = v4[i];
            acc = fmaf(w.x, v.x, acc); acc = fmaf(w.y, v.y, acc);
            acc = fmaf(w.z, v.z, acc); acc = fmaf(w.w, v.w, acc);
        }
        #pragma unroll
        for (int o = 16; o; o >>= 1) acc += __shfl_xor_sync(0xffffffffu, acc, o);
        if (lane == 0) sh[warp] = acc;
        __syncthreads();
        if (tid == 0) {
            atomicAdd(&g_xp[row], sh[0] + sh[1] + sh[2] + sh[3]);
            __threadfence();
            atomicAdd(&c_xp, 1u);
        }
    } else {
        // SSM update for 128 channels
        if (tid == 0) {
            volatile unsigned int* p = &c_xp;
            while (*p < NB_XP) __nanosleep(64);
        }
        __syncthreads();
        __threadfence();
        if (tid < XP_DIM) sh[tid] = __ldcg(&g_xp[tid]);
        __syncthreads();

        const int ch = (b - NB_XP) * 128 + tid;

        float dtr = b_dt[ch];
        const float4* wd4 = (const float4*)(W_dt + (size_t)ch * DT_RANK);
        float4 w0 = wd4[0], w1 = wd4[1];
        dtr = fmaf(w0.x, sh[0], dtr); dtr = fmaf(w0.y, sh[1], dtr);
        dtr = fmaf(w0.z, sh[2], dtr); dtr = fmaf(w0.w, sh[3], dtr);
        dtr = fmaf(w1.x, sh[4], dtr); dtr = fmaf(w1.y, sh[5], dtr);
        dtr = fmaf(w1.z, sh[6], dtr); dtr = fmaf(w1.w, sh[7], dtr);
        float dt = (dtr > 20.0f) ? dtr : log1pf(expf(dtr));

        const float xc = g_x_conv[ch];
        const float* al = A_log + (size_t)ch * D_STATE;
        const float* st = ssm_state + (size_t)ch * D_STATE;
        float* hout = out + D_MODEL + (size_t)ch * D_STATE;

        float acc = 0.0f;
        #pragma unroll
        for (int s = 0; s < D_STATE; s++) {
            float A    = -expf(al[s]);
            float abar = expf(dt * A);
            float h    = fmaf(abar, st[s], dt * sh[DT_RANK + s] * xc);
            hout[s] = h;
            acc = fmaf(h, sh[DT_RANK + D_STATE + s], acc);
        }
        g_y[ch] = fmaf(D_param[ch], xc, acc) * g_z_silu[ch];
    }
}

// ---------------------------------------------------------------------------
// Kernel 3 (PDL secondary): out += W_out @ y. Warp per (row, K-quarter),
// 8KB contiguous stream per warp, y-quarter staged to smem. grid = 4096.
// Block 0 resets c_xp for the next graph replay.
// ---------------------------------------------------------------------------
__global__ __launch_bounds__(128, 16) void k_wout(
    const float* __restrict__ W_out,
    float* __restrict__ out)
{
    __shared__ float4 sy[512];          // 8 KB
    const int tid  = threadIdx.x;
    const int lane = tid & 31;
    const int warp = tid >> 5;
    const int idx  = blockIdx.x;
    const int q    = idx >> 10;                    // K-quarter 0..3
    const int row  = (idx & 1023) * 4 + warp;
    const int kb4  = q * 512;

    cudaGridDependencySynchronize();    // k_mid outputs visible after this
    if (idx == 0 && tid == 0) c_xp = 0;            // reset for next replay

    const float4* y4 = (const float4*)g_y + kb4;
    #pragma unroll
    for (int i = tid; i < 512; i += 128) sy[i] = y4[i];
    __syncthreads();

    const float4* w4 = (const float4*)(W_out + (size_t)row * D_INNER) + kb4;
    float acc0 = 0.0f, acc1 = 0.0f;
    #pragma unroll
    for (int i = lane; i < 512; i += 64) {
        float4 wa = __ldcs(&w4[i]);
        float4 wb = __ldcs(&w4[i + 32]);
        float4 va = sy[i];
        float4 vb = sy[i + 32];
        acc0 = fmaf(wa.x, va.x, acc0); acc0 = fmaf(wa.y, va.y, acc0);
        acc0 = fmaf(wa.z, va.z, acc0); acc0 = fmaf(wa.w, va.w, acc0);
        acc1 = fmaf(wb.x, vb.x, acc1); acc1 = fmaf(wb.y, vb.y, acc1);
        acc1 = fmaf(wb.z, vb.z, acc1); acc1 = fmaf(wb.w, vb.w, acc1);
    }
    float acc = acc0 + acc1;
    #pragma unroll
    for (int o = 16; o; o >>= 1) acc += __shfl_xor_sync(0xffffffffu, acc, o);
    if (lane == 0) atomicAdd(&out[row], acc);
}

// ---------------------------------------------------------------------------
extern "C" void kernel_launch(void* const* d_in, const int* in_sizes, int n_in,
                              void* d_out, int out_size)
{
    const float* x           = (const float*)d_in[0];
    const float* ssm_state   = (const float*)d_in[1];
    const float* conv_buffer = (const float*)d_in[2];
    const float* W_in        = (const float*)d_in[3];
    const float* conv_w      = (const float*)d_in[4];
    const float* conv_b      = (const float*)d_in[5];
    const float* W_xp        = (const float*)d_in[6];
    const float* W_dt        = (const float*)d_in[7];
    const float* b_dt        = (const float*)d_in[8];
    const float* A_log       = (const float*)d_in[9];
    const float* D_param     = (const float*)d_in[10];
    const float* W_out       = (const float*)d_in[11];
    float* out = (float*)d_out;

    // 1) W_in GEMV (normal launch)
    k_win<<<4096, 128>>>(W_in, x, conv_buffer, conv_w, conv_b, out);

    // PDL attribute for dependent kernels
    cudaLaunchAttribute attrs[1];
    attrs[0].id = cudaLaunchAttributeProgrammaticStreamSerialization;
    attrs[0].val.programmaticStreamSerializationAllowed = 1;

    // 2) xp + ssm (PDL on k_win)
    {
        cudaLaunchConfig_t cfg = {};
        cfg.gridDim  = dim3(NB_MID, 1, 1);
        cfg.blockDim = dim3(128, 1, 1);
        cfg.attrs    = attrs;
        cfg.numAttrs = 1;
        cudaLaunchKernelEx(&cfg, k_mid, W_xp, W_dt, b_dt, ssm_state,
                           A_log, D_param, out);
    }

    // 3) W_out GEMV (PDL on k_mid)
    {
        cudaLaunchConfig_t cfg = {};
        cfg.gridDim  = dim3(4096, 1, 1);
        cfg.blockDim = dim3(128, 1, 1);
        cfg.attrs    = attrs;
        cfg.numAttrs = 1;
        cudaLaunchKernelEx(&cfg, k_wout, W_out, out);
    }
}

// round 11
// speedup vs baseline: 1.1631x; 1.0342x over previous
#include <cuda_runtime.h>
#include <cuda_pipeline.h>
#include <math.h>

#define D_INNER 8192
#define D_MODEL 4096
#define DT_RANK 8
#define D_STATE 16
#define XP_DIM  (DT_RANK + 2 * D_STATE)   // 40

#define NB_XP    320                      // 40 rows x 8 K-chunks of 1024
#define NB_SSM   64
#define B_WOUT0  (NB_XP + NB_SSM)         // 384
#define NB_WOUT  4096
#define NB_TAIL  (B_WOUT0 + NB_WOUT)      // 4480

// Scratch + flags
__device__ float g_x_conv[D_INNER];
__device__ float g_z_silu[D_INNER];
__device__ float g_xp[XP_DIM];
__device__ float g_y[D_INNER];
__device__ unsigned int c_xp, c_ssm;

__device__ __forceinline__ void spin_until(volatile unsigned int* p, unsigned int v) {
    while (*p < v) __nanosleep(64);
}

// ---------------------------------------------------------------------------
// Kernel 1: xz = W_in @ x (16384 x 4096) + fused conv/silu epilogue.
// Warp-per-row, 128thr, 16 blocks/SM. Blocks 0-31 zero out[0:4096];
// block 0 zeroes g_xp and resets counters. grid = 4096.
// ---------------------------------------------------------------------------
__global__ __launch_bounds__(128, 16) void k_win(
    const float* __restrict__ W_in,
    const float* __restrict__ x,
    const float* __restrict__ conv_buffer,
    const float* __restrict__ conv_w,
    const float* __restrict__ conv_b,
    float* __restrict__ out)
{
    const int tid  = threadIdx.x;
    const int lane = tid & 31;
    const int warp = tid >> 5;
    if (blockIdx.x < 32) out[blockIdx.x * 128 + tid] = 0.0f;
    if (blockIdx.x == 0) {
        if (tid < XP_DIM) g_xp[tid] = 0.0f;
        if (tid == 0) { c_xp = 0; c_ssm = 0; }
    }

    const int row = blockIdx.x * 4 + warp;
    const float4* w4 = (const float4*)(W_in + (size_t)row * D_MODEL);
    const float4* x4 = (const float4*)x;

    float acc0 = 0.0f, acc1 = 0.0f;
    #pragma unroll
    for (int i = lane; i < D_MODEL / 4; i += 64) {
        float4 wa = __ldcs(&w4[i]);
        float4 wb = __ldcs(&w4[i + 32]);
        float4 va = x4[i];
        float4 vb = x4[i + 32];
        acc0 = fmaf(wa.x, va.x, acc0); acc0 = fmaf(wa.y, va.y, acc0);
        acc0 = fmaf(wa.z, va.z, acc0); acc0 = fmaf(wa.w, va.w, acc0);
        acc1 = fmaf(wb.x, vb.x, acc1); acc1 = fmaf(wb.y, vb.y, acc1);
        acc1 = fmaf(wb.z, vb.z, acc1); acc1 = fmaf(wb.w, vb.w, acc1);
    }
    float acc = acc0 + acc1;
    #pragma unroll
    for (int o = 16; o; o >>= 1) acc += __shfl_xor_sync(0xffffffffu, acc, o);

    if (lane == 0) {
        if (row < D_INNER) {
            float b1 = conv_buffer[row * 3 + 1];
            float b2 = conv_buffer[row * 3 + 2];
            float4 cw = ((const float4*)conv_w)[row];
            float s = fmaf(b1, cw.x, fmaf(b2, cw.y,
                       fmaf(acc, cw.z, fmaf(acc, cw.w, conv_b[row]))));
            g_x_conv[row] = s / (1.0f + expf(-s));
        } else {
            g_z_silu[row - D_INNER] = acc / (1.0f + expf(-acc));
        }
    }
}

// ---------------------------------------------------------------------------
// Kernel 2 (tail): xp (blocks 0-319) + ssm (320-383) + W_out GEMV (384+).
// wout blocks prefetch their first 2KB/warp of W_out via cp.async BEFORE
// spinning on c_ssm, so the xp/ssm window streams weights at full BW.
// Dependencies strictly monotone in blockIdx; all dep targets in wave 1.
// ---------------------------------------------------------------------------
__global__ __launch_bounds__(128, 16) void k_tail(
    const float* __restrict__ W_xp,
    const float* __restrict__ W_dt,
    const float* __restrict__ b_dt,
    const float* __restrict__ ssm_state,
    const float* __restrict__ A_log,
    const float* __restrict__ D_param,
    const float* __restrict__ W_out,
    float* __restrict__ out)
{
    __shared__ float4 sw[512];            // 8 KB (wout prefetch / xp+ssm scratch)
    float* sh = (float*)sw;
    const int b    = blockIdx.x;
    const int tid  = threadIdx.x;
    const int lane = tid & 31;
    const int warp = tid >> 5;

    if (b < NB_XP) {
        // ---------------- xp = W_xp @ x_conv (split-K chunk) ----------------
        const int row = b % XP_DIM;
        const int kb  = (b / XP_DIM) * 1024;
        const float4* w4 = (const float4*)(W_xp + (size_t)row * D_INNER + kb);
        const float4* v4 = (const float4*)(g_x_conv + kb);
        float acc = 0.0f;
        #pragma unroll
        for (int i = tid; i < 256; i += 128) {
            float4 w = __ldcs(&w4[i]);
            float4 v = v4[i];
            acc = fmaf(w.x, v.x, acc); acc = fmaf(w.y, v.y, acc);
            acc = fmaf(w.z, v.z, acc); acc = fmaf(w.w, v.w, acc);
        }
        #pragma unroll
        for (int o = 16; o; o >>= 1) acc += __shfl_xor_sync(0xffffffffu, acc, o);
        if (lane == 0) sh[warp] = acc;
        __syncthreads();
        if (tid == 0) {
            atomicAdd(&g_xp[row], sh[0] + sh[1] + sh[2] + sh[3]);
            __threadfence();
            atomicAdd(&c_xp, 1u);
        }

    } else if (b < B_WOUT0) {
        // ---------------- SSM update (128 channels per block) ---------------
        if (tid == 0) spin_until(&c_xp, NB_XP);
        __syncthreads();
        __threadfence();
        if (tid < XP_DIM) sh[tid] = __ldcg(&g_xp[tid]);
        __syncthreads();

        const int ch = (b - NB_XP) * 128 + tid;

        float dtr = b_dt[ch];
        const float4* wd4 = (const float4*)(W_dt + (size_t)ch * DT_RANK);
        float4 w0 = wd4[0], w1 = wd4[1];
        dtr = fmaf(w0.x, sh[0], dtr); dtr = fmaf(w0.y, sh[1], dtr);
        dtr = fmaf(w0.z, sh[2], dtr); dtr = fmaf(w0.w, sh[3], dtr);
        dtr = fmaf(w1.x, sh[4], dtr); dtr = fmaf(w1.y, sh[5], dtr);
        dtr = fmaf(w1.z, sh[6], dtr); dtr = fmaf(w1.w, sh[7], dtr);
        float dt = (dtr > 20.0f) ? dtr : log1pf(expf(dtr));

        const float xc = g_x_conv[ch];
        const float* al = A_log + (size_t)ch * D_STATE;
        const float* st = ssm_state + (size_t)ch * D_STATE;
        float* hout = out + D_MODEL + (size_t)ch * D_STATE;

        float acc = 0.0f;
        #pragma unroll
        for (int s = 0; s < D_STATE; s++) {
            float A    = -expf(al[s]);
            float abar = expf(dt * A);
            float h    = fmaf(abar, st[s], dt * sh[DT_RANK + s] * xc);
            hout[s] = h;
            acc = fmaf(h, sh[DT_RANK + D_STATE + s], acc);
        }
        g_y[ch] = fmaf(D_param[ch], xc, acc) * g_z_silu[ch];
        __syncthreads();
        if (tid == 0) { __threadfence(); atomicAdd(&c_ssm, 1u); }

    } else {
        // ---------------- out += W_out @ y, warp per (row, K-quarter) -------
        const int idx = b - B_WOUT0;          // 0..4095
        const int q   = idx >> 10;            // K-quarter 0..3
        const int row = (idx & 1023) * 4 + warp;
        const int kb4 = q * 512;              // quarter offset in float4s

        const float4* w4 = (const float4*)(W_out + (size_t)row * D_INNER) + kb4;
        const float4* y4 = (const float4*)g_y + kb4;

        // Prefetch first 128 float4 (2KB) of this warp's stream into smem.
        float4* swp = sw + warp * 128;
        #pragma unroll
        for (int k = 0; k < 4; ++k)
            __pipeline_memcpy_async(swp + lane + 32 * k, w4 + lane + 32 * k, 16);
        __pipeline_commit();

        if (tid == 0) spin_until(&c_ssm, NB_SSM);
        __syncthreads();                      // spin result visible to block
        __pipeline_wait_prior(0);             // own cp.asyncs complete

        float acc0 = 0.0f, acc1 = 0.0f;
        // smem part: i in [lane, 128)
        #pragma unroll
        for (int k = 0; k < 4; k += 2) {
            float4 wa = swp[lane + 32 * k];
            float4 wb = swp[lane + 32 * (k + 1)];
            float4 va = __ldg(&y4[lane + 32 * k]);
            float4 vb = __ldg(&y4[lane + 32 * (k + 1)]);
            acc0 = fmaf(wa.x, va.x, acc0); acc0 = fmaf(wa.y, va.y, acc0);
            acc0 = fmaf(wa.z, va.z, acc0); acc0 = fmaf(wa.w, va.w, acc0);
            acc1 = fmaf(wb.x, vb.x, acc1); acc1 = fmaf(wb.y, vb.y, acc1);
            acc1 = fmaf(wb.z, vb.z, acc1); acc1 = fmaf(wb.w, vb.w, acc1);
        }
        // gmem part: i in [128+lane, 512)
        #pragma unroll
        for (int i = 128 + lane; i < 512; i += 64) {
            float4 wa = __ldcs(&w4[i]);
            float4 wb = __ldcs(&w4[i + 32]);
            float4 va = __ldg(&y4[i]);
            float4 vb = __ldg(&y4[i + 32]);
            acc0 = fmaf(wa.x, va.x, acc0); acc0 = fmaf(wa.y, va.y, acc0);
            acc0 = fmaf(wa.z, va.z, acc0); acc0 = fmaf(wa.w, va.w, acc0);
            acc1 = fmaf(wb.x, vb.x, acc1); acc1 = fmaf(wb.y, vb.y, acc1);
            acc1 = fmaf(wb.z, vb.z, acc1); acc1 = fmaf(wb.w, vb.w, acc1);
        }
        float acc = acc0 + acc1;
        #pragma unroll
        for (int o = 16; o; o >>= 1) acc += __shfl_xor_sync(0xffffffffu, acc, o);
        if (lane == 0) atomicAdd(&out[row], acc);
    }
}

// ---------------------------------------------------------------------------
extern "C" void kernel_launch(void* const* d_in, const int* in_sizes, int n_in,
                              void* d_out, int out_size)
{
    const float* x           = (const float*)d_in[0];
    const float* ssm_state   = (const float*)d_in[1];
    const float* conv_buffer = (const float*)d_in[2];
    const float* W_in        = (const float*)d_in[3];
    const float* conv_w      = (const float*)d_in[4];
    const float* conv_b      = (const float*)d_in[5];
    const float* W_xp        = (const float*)d_in[6];
    const float* W_dt        = (const float*)d_in[7];
    const float* b_dt        = (const float*)d_in[8];
    const float* A_log       = (const float*)d_in[9];
    const float* D_param     = (const float*)d_in[10];
    const float* W_out       = (const float*)d_in[11];
    float* out = (float*)d_out;

    k_win <<<4096, 128>>>(W_in, x, conv_buffer, conv_w, conv_b, out);
    k_tail<<<NB_TAIL, 128>>>(W_xp, W_dt, b_dt, ssm_state, A_log, D_param,
                             W_out, out);
}